// round 8
// baseline (speedup 1.0000x reference)
#include <cuda_runtime.h>
#include <cuda_bf16.h>
#include <cstdint>
#include <math.h>

#define BATCH 8192
#define DIM   256
#define BM    128
#define BN    128
#define COLSPER 4096
#define TILES (COLSPER / BN)      // 32
#define THREADS 256
#define NCH    2

#define SCALE_L2 1442.6950408889634f   // 1000 * log2(e)
#define LN2F     0.69314718055994531f
#define MAGICF   12582912.0f           // 2^23 + 2^22
#define MAGICI   0x4B400000

// ---- shared memory layout (dynamic) ----
#define SA     0                        // A tile 128x256 int8 (32KB, swizzled)
#define SBB    32768                    // 3 B tile buffers (32KB each)
#define SMRG_M 131072                   // 128*4 floats (2KB)
#define SMRG_S 133120                   // 128*4 floats (2KB)
#define SMEM_BYTES 135168

// ---- device globals (no allocation allowed) ----
__device__ uint32_t g_zi8[BATCH * DIM / 4];   // packed int8
__device__ uint32_t g_zj8[BATCH * DIM / 4];
__device__ float g_n1[BATCH];
__device__ float g_n2[BATCH];
__device__ float g_diag[BATCH];
__device__ float g_pm[NCH][BATCH];
__device__ float g_ps[NCH][BATCH];
__device__ unsigned int g_absmax_bits;
__device__ float g_loss_sum;
__device__ float g_diag_sum;
__device__ unsigned int g_done;

// ================= PTX helpers =================
__device__ __forceinline__ uint32_t smem_u32(const void* p) {
    uint32_t a;
    asm("{ .reg .u64 t; cvta.to.shared.u64 t, %1; cvt.u32.u64 %0, t; }" : "=r"(a) : "l"(p));
    return a;
}
__device__ __forceinline__ float ex2f(float x) {
    float r; asm("ex2.approx.f32 %0, %1;" : "=f"(r) : "f"(x)); return r;
}
__device__ __forceinline__ void cp16(uint32_t dst, const void* src) {
    asm volatile("cp.async.cg.shared.global [%0], [%1], 16;" :: "r"(dst), "l"(src) : "memory");
}
__device__ __forceinline__ void cp_commit() { asm volatile("cp.async.commit_group;" ::: "memory"); }
template <int N> __device__ __forceinline__ void cp_wait() {
    asm volatile("cp.async.wait_group %0;" :: "n"(N) : "memory");
}
__device__ __forceinline__ void ldsm_x4(uint32_t* r, uint32_t addr) {
    asm volatile("ldmatrix.sync.aligned.m8n8.x4.shared.b16 {%0,%1,%2,%3}, [%4];\n"
                 : "=r"(r[0]), "=r"(r[1]), "=r"(r[2]), "=r"(r[3])
                 : "r"(addr));
}
__device__ __forceinline__ void mma_s8(int* d, const uint32_t* a, const uint32_t* b) {
    asm volatile(
        "mma.sync.aligned.m16n8k32.row.col.s32.s8.s8.s32 "
        "{%0,%1,%2,%3}, {%4,%5,%6,%7}, {%8,%9}, {%0,%1,%2,%3};\n"
        : "+r"(d[0]), "+r"(d[1]), "+r"(d[2]), "+r"(d[3])
        : "r"(a[0]), "r"(a[1]), "r"(a[2]), "r"(a[3]), "r"(b[0]), "r"(b[1]));
}

// swizzled chunk position inside a 256B row: chunk c in 0..15
__device__ __forceinline__ uint32_t chunk_pos(int r, int c) {
    return (uint32_t)(((c & 8) | ((c ^ r) & 7)) << 4);
}

// load a 128x256 int8 tile (32KB) into swizzled smem via cp.async (256 threads)
__device__ __forceinline__ void load_tile(uint32_t dst, const uint32_t* src, int tid) {
    const char* s = (const char*)src;
    #pragma unroll
    for (int i = 0; i < 8; i++) {
        int idx = tid + i * THREADS;       // 0..2047
        int r = idx >> 4;                  // row 0..127
        int c = idx & 15;
        cp16(dst + r * 256 + chunk_pos(r, c), s + (size_t)r * 256 + (size_t)c * 16);
    }
}

// ================= kernels =================
__global__ void cl_init_kernel() {
    g_diag_sum = 0.0f;
    g_loss_sum = 0.0f;
    g_absmax_bits = 0u;
    g_done = 0u;
}

// pass 1: row norms, exact fp32 diagonal, global max |z| (post-normalize)
__global__ void cl_prep_kernel(const float* __restrict__ p1,
                               const float* __restrict__ p2) {
    int row = blockIdx.x;
    int t = threadIdx.x;

    float v1 = p1[row * DIM + t];
    float v2 = p2[row * DIM + t];

    float s1 = v1 * v1, s2 = v2 * v2, s3 = v1 * v2;
    #pragma unroll
    for (int o = 16; o > 0; o >>= 1) {
        s1 += __shfl_down_sync(0xffffffffu, s1, o);
        s2 += __shfl_down_sync(0xffffffffu, s2, o);
        s3 += __shfl_down_sync(0xffffffffu, s3, o);
    }
    __shared__ float sh1[8], sh2[8], sh3[8], shm[8];
    __shared__ float rn1, rn2;
    int wid = t >> 5;
    if ((t & 31) == 0) { sh1[wid] = s1; sh2[wid] = s2; sh3[wid] = s3; }
    __syncthreads();
    if (t == 0) {
        float a = 0.f, b = 0.f, c = 0.f;
        #pragma unroll
        for (int i = 0; i < 8; i++) { a += sh1[i]; b += sh2[i]; c += sh3[i]; }
        float n1 = fmaxf(sqrtf(a), 1e-12f);
        float n2 = fmaxf(sqrtf(b), 1e-12f);
        rn1 = n1; rn2 = n2;
        g_n1[row] = n1;
        g_n2[row] = n2;
        g_diag[row] = c / (n1 * n2);
    }
    __syncthreads();
    float mx = fmaxf(fabsf(v1) / rn1, fabsf(v2) / rn2);
    #pragma unroll
    for (int o = 16; o > 0; o >>= 1)
        mx = fmaxf(mx, __shfl_down_sync(0xffffffffu, mx, o));
    if ((t & 31) == 0) shm[wid] = mx;
    __syncthreads();
    if (t == 0) {
        float m = shm[0];
        #pragma unroll
        for (int i = 1; i < 8; i++) m = fmaxf(m, shm[i]);
        atomicMax(&g_absmax_bits, __float_as_uint(m));   // positive floats: bit-monotone
    }
}

// pass 2: quantize both tensors to int8 with the exact global scale
__global__ void cl_quant_kernel(const float* __restrict__ p1,
                                const float* __restrict__ p2) {
    int g = blockIdx.x * 256 + threadIdx.x;
    int row = g >> 6;
    float S = __uint_as_float(g_absmax_bits);
    float q = 127.0f / S;
    float q1 = q / g_n1[row];
    float q2 = q / g_n2[row];

    float4 a = ((const float4*)p1)[g];
    float4 b = ((const float4*)p2)[g];

    int a0 = __float2int_rn(a.x * q1), a1 = __float2int_rn(a.y * q1);
    int a2 = __float2int_rn(a.z * q1), a3 = __float2int_rn(a.w * q1);
    int b0 = __float2int_rn(b.x * q2), b1 = __float2int_rn(b.y * q2);
    int b2 = __float2int_rn(b.z * q2), b3 = __float2int_rn(b.w * q2);

    g_zi8[g] = (a0 & 0xff) | ((a1 & 0xff) << 8) | ((a2 & 0xff) << 16) | (a3 << 24);
    g_zj8[g] = (b0 & 0xff) | ((b1 & 0xff) << 8) | ((b2 & 0xff) << 16) | (b3 << 24);
}

// fused int8 IMMA GEMM + online LSE; 3-stage B pipeline, ONE sync per tile,
// cold-slot-skip epilogue. grid = 128 (64 row-blocks x 2 col-halves);
// 8 warps as 2x4 over the 128x128 tile -> warp tile 64x32
__global__ void __launch_bounds__(THREADS, 1)
cl_main_kernel() {
    extern __shared__ char smem[];
    uint32_t sb = smem_u32(smem);
    const int tid  = threadIdx.x;
    const int warp = tid >> 5;
    const int lane = tid & 31;
    const int warp_m = warp >> 2;       // 0..1 : 64 rows
    const int warp_n = warp & 3;        // 0..3 : 32 cols
    const int rb   = (blockIdx.x >> 1) * BM;
    const int ch   = blockIdx.x & 1;
    const int col0 = ch * COLSPER;

    const float S = __uint_as_float(g_absmax_bits);
    const float kk = SCALE_L2 * (S * S) * (1.0f / 16129.0f);
    const float TSKIP = 30.0f / kk;     // skip slots > 30 log2-units below running max

    // prologue: A+B0 (G0), B1 (G1), B2 (G2)
    load_tile(sb + SA,        g_zi8 + (size_t)rb * (DIM / 4), tid);
    load_tile(sb + SBB,       g_zj8 + (size_t)col0 * (DIM / 4), tid);
    cp_commit();
    load_tile(sb + SBB + 32768, g_zj8 + (size_t)(col0 + BN) * (DIM / 4), tid);
    cp_commit();
    load_tile(sb + SBB + 65536, g_zj8 + (size_t)(col0 + 2 * BN) * (DIM / 4), tid);
    cp_commit();
    cp_wait<2>();              // A + B0 resident
    __syncthreads();

    float m_run[8], s_run[8];
    #pragma unroll
    for (int i = 0; i < 8; i++) { m_run[i] = -1.0e9f; s_run[i] = 0.0f; }

    const int mrow = lane & 7;
    const int am = lane >> 3;
    int bufsel = 0;

    for (int t = 0; t < TILES; ++t) {
        const uint32_t bbase = sb + SBB + (uint32_t)bufsel * 32768;

        int acc[4][4][4];
        #pragma unroll
        for (int mi = 0; mi < 4; mi++)
            #pragma unroll
            for (int ni = 0; ni < 4; ni++)
                #pragma unroll
                for (int q = 0; q < 4; q++)
                    acc[mi][ni][q] = 0;

        #pragma unroll
        for (int ks = 0; ks < 8; ks++) {
            uint32_t a[4][4];
            {
                int achk = 2 * ks + (am >> 1);
                #pragma unroll
                for (int mi = 0; mi < 4; mi++) {
                    int row = warp_m * 64 + mi * 16 + ((am & 1) << 3) + mrow;
                    ldsm_x4(a[mi], sb + SA + row * 256 + chunk_pos(row, achk));
                }
            }
            uint32_t b[4][2];
            {
                int bchk = 2 * ks + (am & 1);
                #pragma unroll
                for (int np = 0; np < 2; np++) {
                    int col = warp_n * 32 + np * 16 + ((am >> 1) << 3) + mrow;
                    uint32_t r4[4];
                    ldsm_x4(r4, bbase + col * 256 + chunk_pos(col, bchk));
                    b[np * 2][0] = r4[0];     b[np * 2][1] = r4[1];
                    b[np * 2 + 1][0] = r4[2]; b[np * 2 + 1][1] = r4[3];
                }
            }
            #pragma unroll
            for (int mi = 0; mi < 4; mi++)
                #pragma unroll
                for (int ni = 0; ni < 4; ni++)
                    mma_s8(acc[mi][ni], a[mi], b[ni]);
        }

        // ---- epilogue: online LSE update with cold-slot skip ----
        // (overlaps the cp.async prefetch issued last iteration)
        #pragma unroll
        for (int mi = 0; mi < 4; mi++) {
            #pragma unroll
            for (int h = 0; h < 2; h++) {
                int idx = mi * 2 + h;
                int y[8];
                #pragma unroll
                for (int ni = 0; ni < 4; ni++) {
                    y[ni * 2]     = acc[mi][ni][h * 2];
                    y[ni * 2 + 1] = acc[mi][ni][h * 2 + 1];
                }
                int t0 = max(y[0], y[1]), t1 = max(y[2], y[3]);
                int t2 = max(y[4], y[5]), t3 = max(y[6], y[7]);
                int tmi = max(max(t0, t1), max(t2, t3));
                float ftmi = __int_as_float(tmi + MAGICI) - MAGICF;   // exact int->float
                if (ftmi >= m_run[idx] - TSKIP) {                      // hot slot only
                    float nm = fmaxf(m_run[idx], ftmi);
                    float nb = -(nm + MAGICF) * kk;
                    float a0 = 0.f, a1 = 0.f;
                    #pragma unroll
                    for (int j = 0; j < 4; j++) {
                        a0 += ex2f(fmaf(__int_as_float(y[2 * j] + MAGICI), kk, nb));
                        a1 += ex2f(fmaf(__int_as_float(y[2 * j + 1] + MAGICI), kk, nb));
                    }
                    s_run[idx] = s_run[idx] * ex2f((m_run[idx] - nm) * kk) + (a0 + a1);
                    m_run[idx] = nm;
                }
            }
        }

        // B[t+1] complete (1 younger group may stay in flight), then single sync:
        // publishes B[t+1] AND confirms all warps finished reading buf[t%3]
        cp_wait<1>();
        __syncthreads();

        // prefetch B[t+3] into the buffer consumed by THIS tile
        if (t + 3 < TILES)
            load_tile(bbase, g_zj8 + (size_t)(col0 + (t + 3) * BN) * (DIM / 4), tid);
        cp_commit();   // uniform group counting (empty group near the end)

        bufsel = (bufsel == 2) ? 0 : bufsel + 1;
    }

    // ---- reduce across lanes sharing a row (lane&3 varies) ----
    #pragma unroll
    for (int idx = 0; idx < 8; idx++) {
        #pragma unroll
        for (int o = 1; o <= 2; o <<= 1) {
            float om = __shfl_xor_sync(0xffffffffu, m_run[idx], o);
            float os = __shfl_xor_sync(0xffffffffu, s_run[idx], o);
            float nm = fmaxf(m_run[idx], om);
            s_run[idx] = s_run[idx] * ex2f((m_run[idx] - nm) * kk)
                       + os         * ex2f((om         - nm) * kk);
            m_run[idx] = nm;
        }
    }

    // ---- merge across the 4 column-warps via smem ----
    float* mrg_m = (float*)(smem + SMRG_M);
    float* mrg_s = (float*)(smem + SMRG_S);
    if ((lane & 3) == 0) {
        #pragma unroll
        for (int idx = 0; idx < 8; idx++) {
            int row = warp_m * 64 + (idx >> 1) * 16 + (idx & 1) * 8 + (lane >> 2);
            mrg_m[row * 4 + warp_n] = m_run[idx];
            mrg_s[row * 4 + warp_n] = s_run[idx];
        }
    }
    __syncthreads();

    if (tid < BM) {
        int row = tid;
        float m = mrg_m[row * 4];
        #pragma unroll
        for (int w = 1; w < 4; w++) m = fmaxf(m, mrg_m[row * 4 + w]);
        float s = 0.0f;
        #pragma unroll
        for (int w = 0; w < 4; w++)
            s += mrg_s[row * 4 + w] * ex2f((mrg_m[row * 4 + w] - m) * kk);
        g_pm[ch][rb + row] = m;
        g_ps[ch][rb + row] = s;
    }
}

// merge the column-half partials per row, reduce loss + diag, last block writes out
__global__ void cl_merge_kernel(float* out, int out_size) {
    int r = blockIdx.x * 256 + threadIdx.x;
    float S = __uint_as_float(g_absmax_bits);
    float kk = SCALE_L2 * (S * S) * (1.0f / 16129.0f);

    float m = g_pm[0][r];
    #pragma unroll
    for (int c = 1; c < NCH; c++) m = fmaxf(m, g_pm[c][r]);
    float s = 0.0f;
    #pragma unroll
    for (int c = 0; c < NCH; c++)
        s += g_ps[c][r] * ex2f((g_pm[c][r] - m) * kk);

    float d = g_diag[r];
    float loss = LN2F * fmaf(m, kk, log2f(s)) - 1000.0f * d;
    float ds = d;
    #pragma unroll
    for (int o = 16; o; o >>= 1) {
        loss += __shfl_down_sync(0xffffffffu, loss, o);
        ds   += __shfl_down_sync(0xffffffffu, ds, o);
    }
    __shared__ float sl[8], sd[8];
    if ((threadIdx.x & 31) == 0) { sl[threadIdx.x >> 5] = loss; sd[threadIdx.x >> 5] = ds; }
    __syncthreads();
    if (threadIdx.x == 0) {
        float L = 0.f, D = 0.f;
        #pragma unroll
        for (int i = 0; i < 8; i++) { L += sl[i]; D += sd[i]; }
        atomicAdd(&g_loss_sum, L);
        atomicAdd(&g_diag_sum, D);
        __threadfence();
        unsigned int ticket = atomicAdd(&g_done, 1u);
        if (ticket == gridDim.x - 1) {      // last block: sums complete
            if (out_size > 0) out[0] = *(volatile float*)&g_loss_sum / (float)BATCH;
            if (out_size > 1) out[1] = *(volatile float*)&g_diag_sum;
        }
    }
}

// ================= launch =================
extern "C" void kernel_launch(void* const* d_in, const int* in_sizes, int n_in,
                              void* d_out, int out_size) {
    const float* p1 = (const float*)d_in[0];
    const float* p2 = (const float*)d_in[1];
    float* out = (float*)d_out;

    cudaFuncSetAttribute(cl_main_kernel,
                         cudaFuncAttributeMaxDynamicSharedMemorySize, SMEM_BYTES);

    cl_init_kernel<<<1, 1>>>();
    cl_prep_kernel<<<BATCH, DIM>>>(p1, p2);
    cl_quant_kernel<<<BATCH * DIM / 4 / 256, 256>>>(p1, p2);
    cl_main_kernel<<<BATCH / BM * NCH, THREADS, SMEM_BYTES>>>();
    cl_merge_kernel<<<BATCH / 256, 256>>>(out, out_size);
}

// round 9
// speedup vs baseline: 1.0606x; 1.0606x over previous
#include <cuda_runtime.h>
#include <cuda_bf16.h>
#include <cstdint>
#include <math.h>

#define BATCH 8192
#define DIM   256
#define BM    128
#define BN    128
#define COLSPER 4096
#define TILES (COLSPER / BN)      // 32
#define THREADS 256
#define NCH    2

#define SCALE_L2 1442.6950408889634f   // 1000 * log2(e)
#define LN2F     0.69314718055994531f
#define MAGICF   12582912.0f           // 2^23 + 2^22
#define MAGICI   0x4B400000

// ---- shared memory layout (dynamic) ----
#define SA     0                        // A tile 128x256 int8 (32KB, swizzled)
#define SB0    32768                    // B tile buf0 (32KB)
#define SB1    65536                    // B tile buf1 (32KB)
#define SMRG_M 98304                    // 128*4 floats (2KB)
#define SMRG_S 100352                   // 128*4 floats (2KB)
#define SMEM_BYTES 102400

// ---- device globals (no allocation allowed) ----
__device__ uint32_t g_zi8[BATCH * DIM / 4];   // packed int8
__device__ uint32_t g_zj8[BATCH * DIM / 4];
__device__ float g_n1[BATCH];
__device__ float g_n2[BATCH];
__device__ float g_diag[BATCH];
__device__ float g_pm[NCH][BATCH];
__device__ float g_ps[NCH][BATCH];
__device__ unsigned int g_absmax_bits;
__device__ float g_loss_sum;
__device__ float g_diag_sum;
__device__ unsigned int g_done;

// ================= PTX helpers =================
__device__ __forceinline__ uint32_t smem_u32(const void* p) {
    uint32_t a;
    asm("{ .reg .u64 t; cvta.to.shared.u64 t, %1; cvt.u32.u64 %0, t; }" : "=r"(a) : "l"(p));
    return a;
}
__device__ __forceinline__ float ex2f(float x) {
    float r; asm("ex2.approx.f32 %0, %1;" : "=f"(r) : "f"(x)); return r;
}
__device__ __forceinline__ void cp16(uint32_t dst, const void* src) {
    asm volatile("cp.async.cg.shared.global [%0], [%1], 16;" :: "r"(dst), "l"(src) : "memory");
}
__device__ __forceinline__ void cp_commit() { asm volatile("cp.async.commit_group;" ::: "memory"); }
template <int N> __device__ __forceinline__ void cp_wait() {
    asm volatile("cp.async.wait_group %0;" :: "n"(N) : "memory");
}
__device__ __forceinline__ void ldsm_x4(uint32_t* r, uint32_t addr) {
    asm volatile("ldmatrix.sync.aligned.m8n8.x4.shared.b16 {%0,%1,%2,%3}, [%4];\n"
                 : "=r"(r[0]), "=r"(r[1]), "=r"(r[2]), "=r"(r[3])
                 : "r"(addr));
}
__device__ __forceinline__ void mma_s8(int* d, const uint32_t* a, const uint32_t* b) {
    asm volatile(
        "mma.sync.aligned.m16n8k32.row.col.s32.s8.s8.s32 "
        "{%0,%1,%2,%3}, {%4,%5,%6,%7}, {%8,%9}, {%0,%1,%2,%3};\n"
        : "+r"(d[0]), "+r"(d[1]), "+r"(d[2]), "+r"(d[3])
        : "r"(a[0]), "r"(a[1]), "r"(a[2]), "r"(a[3]), "r"(b[0]), "r"(b[1]));
}

// swizzled chunk position inside a 256B row: chunk c in 0..15
__device__ __forceinline__ uint32_t chunk_pos(int r, int c) {
    return (uint32_t)(((c & 8) | ((c ^ r) & 7)) << 4);
}

// load a 128x256 int8 tile (32KB) into swizzled smem via cp.async (256 threads)
__device__ __forceinline__ void load_tile(uint32_t dst, const uint32_t* src, int tid) {
    const char* s = (const char*)src;
    #pragma unroll
    for (int i = 0; i < 8; i++) {
        int idx = tid + i * THREADS;       // 0..2047
        int r = idx >> 4;                  // row 0..127
        int c = idx & 15;
        cp16(dst + r * 256 + chunk_pos(r, c), s + (size_t)r * 256 + (size_t)c * 16);
    }
}

// ================= kernels =================
__global__ void cl_init_kernel() {
    g_diag_sum = 0.0f;
    g_loss_sum = 0.0f;
    g_absmax_bits = 0u;
    g_done = 0u;
}

// pass 1: row norms, exact fp32 diagonal, global max |z| (post-normalize)
__global__ void cl_prep_kernel(const float* __restrict__ p1,
                               const float* __restrict__ p2) {
    int row = blockIdx.x;
    int t = threadIdx.x;

    float v1 = p1[row * DIM + t];
    float v2 = p2[row * DIM + t];

    float s1 = v1 * v1, s2 = v2 * v2, s3 = v1 * v2;
    #pragma unroll
    for (int o = 16; o > 0; o >>= 1) {
        s1 += __shfl_down_sync(0xffffffffu, s1, o);
        s2 += __shfl_down_sync(0xffffffffu, s2, o);
        s3 += __shfl_down_sync(0xffffffffu, s3, o);
    }
    __shared__ float sh1[8], sh2[8], sh3[8], shm[8];
    __shared__ float rn1, rn2;
    int wid = t >> 5;
    if ((t & 31) == 0) { sh1[wid] = s1; sh2[wid] = s2; sh3[wid] = s3; }
    __syncthreads();
    if (t == 0) {
        float a = 0.f, b = 0.f, c = 0.f;
        #pragma unroll
        for (int i = 0; i < 8; i++) { a += sh1[i]; b += sh2[i]; c += sh3[i]; }
        float n1 = fmaxf(sqrtf(a), 1e-12f);
        float n2 = fmaxf(sqrtf(b), 1e-12f);
        rn1 = n1; rn2 = n2;
        g_n1[row] = n1;
        g_n2[row] = n2;
        g_diag[row] = c / (n1 * n2);
    }
    __syncthreads();
    float mx = fmaxf(fabsf(v1) / rn1, fabsf(v2) / rn2);
    #pragma unroll
    for (int o = 16; o > 0; o >>= 1)
        mx = fmaxf(mx, __shfl_down_sync(0xffffffffu, mx, o));
    if ((t & 31) == 0) shm[wid] = mx;
    __syncthreads();
    if (t == 0) {
        float m = shm[0];
        #pragma unroll
        for (int i = 1; i < 8; i++) m = fmaxf(m, shm[i]);
        atomicMax(&g_absmax_bits, __float_as_uint(m));   // positive floats: bit-monotone
    }
}

// pass 2: quantize both tensors to int8 with the exact global scale
__global__ void cl_quant_kernel(const float* __restrict__ p1,
                                const float* __restrict__ p2) {
    int g = blockIdx.x * 256 + threadIdx.x;
    int row = g >> 6;
    float S = __uint_as_float(g_absmax_bits);
    float q = 127.0f / S;
    float q1 = q / g_n1[row];
    float q2 = q / g_n2[row];

    float4 a = ((const float4*)p1)[g];
    float4 b = ((const float4*)p2)[g];

    int a0 = __float2int_rn(a.x * q1), a1 = __float2int_rn(a.y * q1);
    int a2 = __float2int_rn(a.z * q1), a3 = __float2int_rn(a.w * q1);
    int b0 = __float2int_rn(b.x * q2), b1 = __float2int_rn(b.y * q2);
    int b2 = __float2int_rn(b.z * q2), b3 = __float2int_rn(b.w * q2);

    g_zi8[g] = (a0 & 0xff) | ((a1 & 0xff) << 8) | ((a2 & 0xff) << 16) | (a3 << 24);
    g_zj8[g] = (b0 & 0xff) | ((b1 & 0xff) << 8) | ((b2 & 0xff) << 16) | (b3 << 24);
}

// fused int8 IMMA GEMM + online LSE (round-4 structure) + warp-uniform slot skip.
// grid = 128 (64 row-blocks x 2 col-halves); 8 warps as 2x4 -> warp tile 64x32
__global__ void __launch_bounds__(THREADS, 1)
cl_main_kernel() {
    extern __shared__ char smem[];
    uint32_t sb = smem_u32(smem);
    const int tid  = threadIdx.x;
    const int warp = tid >> 5;
    const int lane = tid & 31;
    const int warp_m = warp >> 2;       // 0..1 : 64 rows
    const int warp_n = warp & 3;        // 0..3 : 32 cols
    const int rb   = (blockIdx.x >> 1) * BM;
    const int ch   = blockIdx.x & 1;
    const int col0 = ch * COLSPER;

    const float S = __uint_as_float(g_absmax_bits);
    const float kk = SCALE_L2 * (S * S) * (1.0f / 16129.0f);
    const float TSKIP = 30.0f / kk;     // 30 log2-units below running max -> negligible

    // prologue: A + B0 (group 0), B1 (group 1)
    load_tile(sb + SA,  g_zi8 + (size_t)rb * (DIM / 4), tid);
    load_tile(sb + SB0, g_zj8 + (size_t)col0 * (DIM / 4), tid);
    cp_commit();
    load_tile(sb + SB1, g_zj8 + (size_t)(col0 + BN) * (DIM / 4), tid);
    cp_commit();
    cp_wait<1>();
    __syncthreads();

    float m_run[8], s_run[8];
    #pragma unroll
    for (int i = 0; i < 8; i++) { m_run[i] = -1.0e9f; s_run[i] = 0.0f; }

    const int mrow = lane & 7;
    const int am = lane >> 3;

    for (int t = 0; t < TILES; ++t) {
        const int sel = t & 1;
        const uint32_t bbase = sb + (sel ? SB1 : SB0);

        int acc[4][4][4];
        #pragma unroll
        for (int mi = 0; mi < 4; mi++)
            #pragma unroll
            for (int ni = 0; ni < 4; ni++)
                #pragma unroll
                for (int q = 0; q < 4; q++)
                    acc[mi][ni][q] = 0;

        #pragma unroll
        for (int ks = 0; ks < 8; ks++) {
            uint32_t a[4][4];
            {
                int achk = 2 * ks + (am >> 1);
                #pragma unroll
                for (int mi = 0; mi < 4; mi++) {
                    int row = warp_m * 64 + mi * 16 + ((am & 1) << 3) + mrow;
                    ldsm_x4(a[mi], sb + SA + row * 256 + chunk_pos(row, achk));
                }
            }
            uint32_t b[4][2];
            {
                int bchk = 2 * ks + (am & 1);
                #pragma unroll
                for (int np = 0; np < 2; np++) {
                    int col = warp_n * 32 + np * 16 + ((am >> 1) << 3) + mrow;
                    uint32_t r4[4];
                    ldsm_x4(r4, bbase + col * 256 + chunk_pos(col, bchk));
                    b[np * 2][0] = r4[0];     b[np * 2][1] = r4[1];
                    b[np * 2 + 1][0] = r4[2]; b[np * 2 + 1][1] = r4[3];
                }
            }
            #pragma unroll
            for (int mi = 0; mi < 4; mi++)
                #pragma unroll
                for (int ni = 0; ni < 4; ni++)
                    mma_s8(acc[mi][ni], a[mi], b[ni]);
        }

        __syncthreads();   // all warps done reading Bs[sel]

        // prefetch B[t+2] into the freed buffer; overlaps epilogue + next tile
        if (t + 2 < TILES) {
            load_tile(bbase, g_zj8 + (size_t)(col0 + (t + 2) * BN) * (DIM / 4), tid);
            cp_commit();
        }

        // ---- epilogue: online LSE update with WARP-UNIFORM slot skip ----
        #pragma unroll
        for (int mi = 0; mi < 4; mi++) {
            #pragma unroll
            for (int h = 0; h < 2; h++) {
                int idx = mi * 2 + h;
                int y[8];
                #pragma unroll
                for (int ni = 0; ni < 4; ni++) {
                    y[ni * 2]     = acc[mi][ni][h * 2];
                    y[ni * 2 + 1] = acc[mi][ni][h * 2 + 1];
                }
                int t0 = max(y[0], y[1]), t1 = max(y[2], y[3]);
                int t2 = max(y[4], y[5]), t3 = max(y[6], y[7]);
                int tmi = max(max(t0, t1), max(t2, t3));
                float ftmi = __int_as_float(tmi + MAGICI) - MAGICF;   // exact int->float
                // warp-uniform vote: enter body iff ANY lane has a hot slot
                bool hot = (ftmi >= m_run[idx] - TSKIP);
                if (__ballot_sync(0xffffffffu, hot)) {
                    float nm = fmaxf(m_run[idx], ftmi);
                    float nb = -(nm + MAGICF) * kk;
                    float a0 = 0.f, a1 = 0.f;
                    #pragma unroll
                    for (int j = 0; j < 4; j++) {
                        a0 += ex2f(fmaf(__int_as_float(y[2 * j] + MAGICI), kk, nb));
                        a1 += ex2f(fmaf(__int_as_float(y[2 * j + 1] + MAGICI), kk, nb));
                    }
                    s_run[idx] = s_run[idx] * ex2f((m_run[idx] - nm) * kk) + (a0 + a1);
                    m_run[idx] = nm;
                }
            }
        }

        if (t + 2 < TILES) cp_wait<1>(); else cp_wait<0>();
        __syncthreads();
    }

    // ---- reduce across lanes sharing a row (lane&3 varies) ----
    #pragma unroll
    for (int idx = 0; idx < 8; idx++) {
        #pragma unroll
        for (int o = 1; o <= 2; o <<= 1) {
            float om = __shfl_xor_sync(0xffffffffu, m_run[idx], o);
            float os = __shfl_xor_sync(0xffffffffu, s_run[idx], o);
            float nm = fmaxf(m_run[idx], om);
            s_run[idx] = s_run[idx] * ex2f((m_run[idx] - nm) * kk)
                       + os         * ex2f((om         - nm) * kk);
            m_run[idx] = nm;
        }
    }

    // ---- merge across the 4 column-warps via smem ----
    float* mrg_m = (float*)(smem + SMRG_M);
    float* mrg_s = (float*)(smem + SMRG_S);
    if ((lane & 3) == 0) {
        #pragma unroll
        for (int idx = 0; idx < 8; idx++) {
            int row = warp_m * 64 + (idx >> 1) * 16 + (idx & 1) * 8 + (lane >> 2);
            mrg_m[row * 4 + warp_n] = m_run[idx];
            mrg_s[row * 4 + warp_n] = s_run[idx];
        }
    }
    __syncthreads();

    if (tid < BM) {
        int row = tid;
        float m = mrg_m[row * 4];
        #pragma unroll
        for (int w = 1; w < 4; w++) m = fmaxf(m, mrg_m[row * 4 + w]);
        float s = 0.0f;
        #pragma unroll
        for (int w = 0; w < 4; w++)
            s += mrg_s[row * 4 + w] * ex2f((mrg_m[row * 4 + w] - m) * kk);
        g_pm[ch][rb + row] = m;
        g_ps[ch][rb + row] = s;
    }
}

// merge the column-half partials per row, reduce loss + diag, last block writes out
__global__ void cl_merge_kernel(float* out, int out_size) {
    int r = blockIdx.x * 256 + threadIdx.x;
    float S = __uint_as_float(g_absmax_bits);
    float kk = SCALE_L2 * (S * S) * (1.0f / 16129.0f);

    float m = g_pm[0][r];
    #pragma unroll
    for (int c = 1; c < NCH; c++) m = fmaxf(m, g_pm[c][r]);
    float s = 0.0f;
    #pragma unroll
    for (int c = 0; c < NCH; c++)
        s += g_ps[c][r] * ex2f((g_pm[c][r] - m) * kk);

    float d = g_diag[r];
    float loss = LN2F * fmaf(m, kk, log2f(s)) - 1000.0f * d;
    float ds = d;
    #pragma unroll
    for (int o = 16; o; o >>= 1) {
        loss += __shfl_down_sync(0xffffffffu, loss, o);
        ds   += __shfl_down_sync(0xffffffffu, ds, o);
    }
    __shared__ float sl[8], sd[8];
    if ((threadIdx.x & 31) == 0) { sl[threadIdx.x >> 5] = loss; sd[threadIdx.x >> 5] = ds; }
    __syncthreads();
    if (threadIdx.x == 0) {
        float L = 0.f, D = 0.f;
        #pragma unroll
        for (int i = 0; i < 8; i++) { L += sl[i]; D += sd[i]; }
        atomicAdd(&g_loss_sum, L);
        atomicAdd(&g_diag_sum, D);
        __threadfence();
        unsigned int ticket = atomicAdd(&g_done, 1u);
        if (ticket == gridDim.x - 1) {      // last block: sums complete
            if (out_size > 0) out[0] = *(volatile float*)&g_loss_sum / (float)BATCH;
            if (out_size > 1) out[1] = *(volatile float*)&g_diag_sum;
        }
    }
}

// ================= launch =================
extern "C" void kernel_launch(void* const* d_in, const int* in_sizes, int n_in,
                              void* d_out, int out_size) {
    const float* p1 = (const float*)d_in[0];
    const float* p2 = (const float*)d_in[1];
    float* out = (float*)d_out;

    cudaFuncSetAttribute(cl_main_kernel,
                         cudaFuncAttributeMaxDynamicSharedMemorySize, SMEM_BYTES);

    cl_init_kernel<<<1, 1>>>();
    cl_prep_kernel<<<BATCH, DIM>>>(p1, p2);
    cl_quant_kernel<<<BATCH * DIM / 4 / 256, 256>>>(p1, p2);
    cl_main_kernel<<<BATCH / BM * NCH, THREADS, SMEM_BYTES>>>();
    cl_merge_kernel<<<BATCH / 256, 256>>>(out, out_size);
}

// round 10
// speedup vs baseline: 1.1979x; 1.1294x over previous
#include <cuda_runtime.h>
#include <cuda_bf16.h>
#include <cstdint>
#include <math.h>

#define BATCH 8192
#define DIM   256
#define BM    128
#define BN    128
#define COLSPER 4096
#define TILES (COLSPER / BN)      // 32
#define THREADS 256
#define NCH    2

#define SCALE_L2 1442.6950408889634f   // 1000 * log2(e)
#define LN2F     0.69314718055994531f
#define MAGICF   12582912.0f           // 2^23 + 2^22
#define MAGICI   0x4B400000

// ---- shared memory layout (dynamic) ----
#define SA     0                        // A tile 128x256 int8 (32KB, swizzled)
#define SB     32768                    // 4 B tile buffers (32KB each)
#define SMRG_M 163840                   // 128*4 floats (2KB)
#define SMRG_S 165888                   // 128*4 floats (2KB)
#define SMEM_BYTES 167936

// ---- device globals (no allocation allowed) ----
__device__ uint32_t g_zi8[BATCH * DIM / 4];   // packed int8
__device__ uint32_t g_zj8[BATCH * DIM / 4];
__device__ float g_n1[BATCH];
__device__ float g_n2[BATCH];
__device__ float g_diag[BATCH];
__device__ float g_pm[NCH][BATCH];
__device__ float g_ps[NCH][BATCH];
__device__ unsigned int g_absmax_bits;
__device__ float g_loss_sum;
__device__ float g_diag_sum;
__device__ unsigned int g_done;

// ================= PTX helpers =================
__device__ __forceinline__ uint32_t smem_u32(const void* p) {
    uint32_t a;
    asm("{ .reg .u64 t; cvta.to.shared.u64 t, %1; cvt.u32.u64 %0, t; }" : "=r"(a) : "l"(p));
    return a;
}
__device__ __forceinline__ float ex2f(float x) {
    float r; asm("ex2.approx.f32 %0, %1;" : "=f"(r) : "f"(x)); return r;
}
__device__ __forceinline__ void cp16(uint32_t dst, const void* src) {
    asm volatile("cp.async.cg.shared.global [%0], [%1], 16;" :: "r"(dst), "l"(src) : "memory");
}
__device__ __forceinline__ void cp_commit() { asm volatile("cp.async.commit_group;" ::: "memory"); }
template <int N> __device__ __forceinline__ void cp_wait() {
    asm volatile("cp.async.wait_group %0;" :: "n"(N) : "memory");
}
__device__ __forceinline__ void ldsm_x4(uint32_t* r, uint32_t addr) {
    asm volatile("ldmatrix.sync.aligned.m8n8.x4.shared.b16 {%0,%1,%2,%3}, [%4];\n"
                 : "=r"(r[0]), "=r"(r[1]), "=r"(r[2]), "=r"(r[3])
                 : "r"(addr));
}
__device__ __forceinline__ void mma_s8(int* d, const uint32_t* a, const uint32_t* b) {
    asm volatile(
        "mma.sync.aligned.m16n8k32.row.col.s32.s8.s8.s32 "
        "{%0,%1,%2,%3}, {%4,%5,%6,%7}, {%8,%9}, {%0,%1,%2,%3};\n"
        : "+r"(d[0]), "+r"(d[1]), "+r"(d[2]), "+r"(d[3])
        : "r"(a[0]), "r"(a[1]), "r"(a[2]), "r"(a[3]), "r"(b[0]), "r"(b[1]));
}

// swizzled chunk position inside a 256B row: chunk c in 0..15
__device__ __forceinline__ uint32_t chunk_pos(int r, int c) {
    return (uint32_t)(((c & 8) | ((c ^ r) & 7)) << 4);
}

// load a 128x256 int8 tile (32KB) into swizzled smem via cp.async (256 threads)
__device__ __forceinline__ void load_tile(uint32_t dst, const uint32_t* src, int tid) {
    const char* s = (const char*)src;
    #pragma unroll
    for (int i = 0; i < 8; i++) {
        int idx = tid + i * THREADS;       // 0..2047
        int r = idx >> 4;                  // row 0..127
        int c = idx & 15;
        cp16(dst + r * 256 + chunk_pos(r, c), s + (size_t)r * 256 + (size_t)c * 16);
    }
}

// one full 128x128x256 tile: MMA loop + straight-line online-LSE epilogue
// (byte-identical math to the round-4 kernel; NO branches in the epilogue)
__device__ __forceinline__ void process_tile(uint32_t sb, uint32_t bbase,
                                             int warp_m, int warp_n, int lane,
                                             float* m_run, float* s_run, float kk) {
    const int mrow = lane & 7;
    const int am = lane >> 3;

    int acc[4][4][4];
    #pragma unroll
    for (int mi = 0; mi < 4; mi++)
        #pragma unroll
        for (int ni = 0; ni < 4; ni++)
            #pragma unroll
            for (int q = 0; q < 4; q++)
                acc[mi][ni][q] = 0;

    #pragma unroll
    for (int ks = 0; ks < 8; ks++) {
        uint32_t a[4][4];
        {
            int achk = 2 * ks + (am >> 1);
            #pragma unroll
            for (int mi = 0; mi < 4; mi++) {
                int row = warp_m * 64 + mi * 16 + ((am & 1) << 3) + mrow;
                ldsm_x4(a[mi], sb + SA + row * 256 + chunk_pos(row, achk));
            }
        }
        uint32_t b[4][2];
        {
            int bchk = 2 * ks + (am & 1);
            #pragma unroll
            for (int np = 0; np < 2; np++) {
                int col = warp_n * 32 + np * 16 + ((am >> 1) << 3) + mrow;
                uint32_t r4[4];
                ldsm_x4(r4, bbase + col * 256 + chunk_pos(col, bchk));
                b[np * 2][0] = r4[0];     b[np * 2][1] = r4[1];
                b[np * 2 + 1][0] = r4[2]; b[np * 2 + 1][1] = r4[3];
            }
        }
        #pragma unroll
        for (int mi = 0; mi < 4; mi++)
            #pragma unroll
            for (int ni = 0; ni < 4; ni++)
                mma_s8(acc[mi][ni], a[mi], b[ni]);
    }

    // ---- epilogue: online LSE update, 8 row-slots x 8 cols of int32 ----
    #pragma unroll
    for (int mi = 0; mi < 4; mi++) {
        #pragma unroll
        for (int h = 0; h < 2; h++) {
            int idx = mi * 2 + h;
            int y[8];
            #pragma unroll
            for (int ni = 0; ni < 4; ni++) {
                y[ni * 2]     = acc[mi][ni][h * 2];
                y[ni * 2 + 1] = acc[mi][ni][h * 2 + 1];
            }
            int t0 = max(y[0], y[1]), t1 = max(y[2], y[3]);
            int t2 = max(y[4], y[5]), t3 = max(y[6], y[7]);
            int tmi = max(max(t0, t1), max(t2, t3));
            float nm = fmaxf(m_run[idx], (float)tmi);
            float nb = -(nm + MAGICF) * kk;           // folds int->float magic bias
            float a0 = 0.f, a1 = 0.f;
            #pragma unroll
            for (int j = 0; j < 4; j++) {
                a0 += ex2f(fmaf(__int_as_float(y[2 * j] + MAGICI), kk, nb));
                a1 += ex2f(fmaf(__int_as_float(y[2 * j + 1] + MAGICI), kk, nb));
            }
            s_run[idx] = s_run[idx] * ex2f((m_run[idx] - nm) * kk) + (a0 + a1);
            m_run[idx] = nm;
        }
    }
}

// ================= kernels =================
__global__ void cl_init_kernel() {
    g_diag_sum = 0.0f;
    g_loss_sum = 0.0f;
    g_absmax_bits = 0u;
    g_done = 0u;
}

// pass 1: row norms, exact fp32 diagonal, global max |z| (post-normalize)
__global__ void cl_prep_kernel(const float* __restrict__ p1,
                               const float* __restrict__ p2) {
    int row = blockIdx.x;
    int t = threadIdx.x;

    float v1 = p1[row * DIM + t];
    float v2 = p2[row * DIM + t];

    float s1 = v1 * v1, s2 = v2 * v2, s3 = v1 * v2;
    #pragma unroll
    for (int o = 16; o > 0; o >>= 1) {
        s1 += __shfl_down_sync(0xffffffffu, s1, o);
        s2 += __shfl_down_sync(0xffffffffu, s2, o);
        s3 += __shfl_down_sync(0xffffffffu, s3, o);
    }
    __shared__ float sh1[8], sh2[8], sh3[8], shm[8];
    __shared__ float rn1, rn2;
    int wid = t >> 5;
    if ((t & 31) == 0) { sh1[wid] = s1; sh2[wid] = s2; sh3[wid] = s3; }
    __syncthreads();
    if (t == 0) {
        float a = 0.f, b = 0.f, c = 0.f;
        #pragma unroll
        for (int i = 0; i < 8; i++) { a += sh1[i]; b += sh2[i]; c += sh3[i]; }
        float n1 = fmaxf(sqrtf(a), 1e-12f);
        float n2 = fmaxf(sqrtf(b), 1e-12f);
        rn1 = n1; rn2 = n2;
        g_n1[row] = n1;
        g_n2[row] = n2;
        g_diag[row] = c / (n1 * n2);
    }
    __syncthreads();
    float mx = fmaxf(fabsf(v1) / rn1, fabsf(v2) / rn2);
    #pragma unroll
    for (int o = 16; o > 0; o >>= 1)
        mx = fmaxf(mx, __shfl_down_sync(0xffffffffu, mx, o));
    if ((t & 31) == 0) shm[wid] = mx;
    __syncthreads();
    if (t == 0) {
        float m = shm[0];
        #pragma unroll
        for (int i = 1; i < 8; i++) m = fmaxf(m, shm[i]);
        atomicMax(&g_absmax_bits, __float_as_uint(m));   // positive floats: bit-monotone
    }
}

// pass 2: quantize both tensors to int8 with the exact global scale
__global__ void cl_quant_kernel(const float* __restrict__ p1,
                                const float* __restrict__ p2) {
    int g = blockIdx.x * 256 + threadIdx.x;
    int row = g >> 6;
    float S = __uint_as_float(g_absmax_bits);
    float q = 127.0f / S;
    float q1 = q / g_n1[row];
    float q2 = q / g_n2[row];

    float4 a = ((const float4*)p1)[g];
    float4 b = ((const float4*)p2)[g];

    int a0 = __float2int_rn(a.x * q1), a1 = __float2int_rn(a.y * q1);
    int a2 = __float2int_rn(a.z * q1), a3 = __float2int_rn(a.w * q1);
    int b0 = __float2int_rn(b.x * q2), b1 = __float2int_rn(b.y * q2);
    int b2 = __float2int_rn(b.z * q2), b3 = __float2int_rn(b.w * q2);

    g_zi8[g] = (a0 & 0xff) | ((a1 & 0xff) << 8) | ((a2 & 0xff) << 16) | (a3 << 24);
    g_zj8[g] = (b0 & 0xff) | ((b1 & 0xff) << 8) | ((b2 & 0xff) << 16) | (b3 << 24);
}

// fused int8 IMMA GEMM + online LSE; 4 B-buffers, ONE barrier per TWO tiles so
// warps drift and overlap MMA with epilogue across warps.
// grid = 128 (64 row-blocks x 2 col-halves); 8 warps as 2x4 -> warp tile 64x32
__global__ void __launch_bounds__(THREADS, 1)
cl_main_kernel() {
    extern __shared__ char smem[];
    uint32_t sb = smem_u32(smem);
    const int tid  = threadIdx.x;
    const int warp = tid >> 5;
    const int lane = tid & 31;
    const int warp_m = warp >> 2;       // 0..1 : 64 rows
    const int warp_n = warp & 3;        // 0..3 : 32 cols
    const int rb   = (blockIdx.x >> 1) * BM;
    const int ch   = blockIdx.x & 1;
    const int col0 = ch * COLSPER;

    const float S = __uint_as_float(g_absmax_bits);
    const float kk = SCALE_L2 * (S * S) * (1.0f / 16129.0f);

    // prologue: A + B0 + B1
    load_tile(sb + SA,      g_zi8 + (size_t)rb * (DIM / 4), tid);
    load_tile(sb + SB,      g_zj8 + (size_t)col0 * (DIM / 4), tid);
    load_tile(sb + SB + 32768, g_zj8 + (size_t)(col0 + BN) * (DIM / 4), tid);
    cp_commit();
    cp_wait<0>();
    __syncthreads();

    float m_run[8], s_run[8];
    #pragma unroll
    for (int i = 0; i < 8; i++) { m_run[i] = -1.0e9f; s_run[i] = 0.0f; }

    for (int u = 0; u < TILES / 2; ++u) {
        const int t0 = 2 * u, t1 = 2 * u + 1;

        // prefetch the NEXT pair into the buffers not read this iteration;
        // those buffers were consumed last pair (guarded by last pair's barrier)
        if (t0 + 2 < TILES) {
            load_tile(sb + SB + (uint32_t)((t0 + 2) & 3) * 32768,
                      g_zj8 + (size_t)(col0 + (t0 + 2) * BN) * (DIM / 4), tid);
            load_tile(sb + SB + (uint32_t)((t1 + 2) & 3) * 32768,
                      g_zj8 + (size_t)(col0 + (t1 + 2) * BN) * (DIM / 4), tid);
            cp_commit();
        }

        // two tiles back-to-back, NO barrier between: warps drift so one
        // warp's epilogue overlaps the other's MMA on the same SMSP
        process_tile(sb, sb + SB + (uint32_t)(t0 & 3) * 32768,
                     warp_m, warp_n, lane, m_run, s_run, kk);
        process_tile(sb, sb + SB + (uint32_t)(t1 & 3) * 32768,
                     warp_m, warp_n, lane, m_run, s_run, kk);

        cp_wait<0>();       // this thread's prefetch arrived
        __syncthreads();    // publish prefetch + all warps done with this pair
    }

    // ---- reduce across lanes sharing a row (lane&3 varies) ----
    #pragma unroll
    for (int idx = 0; idx < 8; idx++) {
        #pragma unroll
        for (int o = 1; o <= 2; o <<= 1) {
            float om = __shfl_xor_sync(0xffffffffu, m_run[idx], o);
            float os = __shfl_xor_sync(0xffffffffu, s_run[idx], o);
            float nm = fmaxf(m_run[idx], om);
            s_run[idx] = s_run[idx] * ex2f((m_run[idx] - nm) * kk)
                       + os         * ex2f((om         - nm) * kk);
            m_run[idx] = nm;
        }
    }

    // ---- merge across the 4 column-warps via smem ----
    float* mrg_m = (float*)(smem + SMRG_M);
    float* mrg_s = (float*)(smem + SMRG_S);
    if ((lane & 3) == 0) {
        #pragma unroll
        for (int idx = 0; idx < 8; idx++) {
            int row = warp_m * 64 + (idx >> 1) * 16 + (idx & 1) * 8 + (lane >> 2);
            mrg_m[row * 4 + warp_n] = m_run[idx];
            mrg_s[row * 4 + warp_n] = s_run[idx];
        }
    }
    __syncthreads();

    if (tid < BM) {
        int row = tid;
        float m = mrg_m[row * 4];
        #pragma unroll
        for (int w = 1; w < 4; w++) m = fmaxf(m, mrg_m[row * 4 + w]);
        float s = 0.0f;
        #pragma unroll
        for (int w = 0; w < 4; w++)
            s += mrg_s[row * 4 + w] * ex2f((mrg_m[row * 4 + w] - m) * kk);
        g_pm[ch][rb + row] = m;
        g_ps[ch][rb + row] = s;
    }
}

// merge the column-half partials per row, reduce loss + diag, last block writes out
__global__ void cl_merge_kernel(float* out, int out_size) {
    int r = blockIdx.x * 256 + threadIdx.x;
    float S = __uint_as_float(g_absmax_bits);
    float kk = SCALE_L2 * (S * S) * (1.0f / 16129.0f);

    float m = g_pm[0][r];
    #pragma unroll
    for (int c = 1; c < NCH; c++) m = fmaxf(m, g_pm[c][r]);
    float s = 0.0f;
    #pragma unroll
    for (int c = 0; c < NCH; c++)
        s += g_ps[c][r] * ex2f((g_pm[c][r] - m) * kk);

    float d = g_diag[r];
    float loss = LN2F * fmaf(m, kk, log2f(s)) - 1000.0f * d;
    float ds = d;
    #pragma unroll
    for (int o = 16; o; o >>= 1) {
        loss += __shfl_down_sync(0xffffffffu, loss, o);
        ds   += __shfl_down_sync(0xffffffffu, ds, o);
    }
    __shared__ float sl[8], sd[8];
    if ((threadIdx.x & 31) == 0) { sl[threadIdx.x >> 5] = loss; sd[threadIdx.x >> 5] = ds; }
    __syncthreads();
    if (threadIdx.x == 0) {
        float L = 0.f, D = 0.f;
        #pragma unroll
        for (int i = 0; i < 8; i++) { L += sl[i]; D += sd[i]; }
        atomicAdd(&g_loss_sum, L);
        atomicAdd(&g_diag_sum, D);
        __threadfence();
        unsigned int ticket = atomicAdd(&g_done, 1u);
        if (ticket == gridDim.x - 1) {      // last block: sums complete
            if (out_size > 0) out[0] = *(volatile float*)&g_loss_sum / (float)BATCH;
            if (out_size > 1) out[1] = *(volatile float*)&g_diag_sum;
        }
    }
}

// ================= launch =================
extern "C" void kernel_launch(void* const* d_in, const int* in_sizes, int n_in,
                              void* d_out, int out_size) {
    const float* p1 = (const float*)d_in[0];
    const float* p2 = (const float*)d_in[1];
    float* out = (float*)d_out;

    cudaFuncSetAttribute(cl_main_kernel,
                         cudaFuncAttributeMaxDynamicSharedMemorySize, SMEM_BYTES);

    cl_init_kernel<<<1, 1>>>();
    cl_prep_kernel<<<BATCH, DIM>>>(p1, p2);
    cl_quant_kernel<<<BATCH * DIM / 4 / 256, 256>>>(p1, p2);
    cl_main_kernel<<<BATCH / BM * NCH, THREADS, SMEM_BYTES>>>();
    cl_merge_kernel<<<BATCH / 256, 256>>>(out, out_size);
}